// round 11
// baseline (speedup 1.0000x reference)
#include <cuda_runtime.h>
#include <cuda_fp16.h>
#include <stdint.h>

#define MAXN 50000
#define MAXE 800000
#define XD 32
#define HD 96
#define OD 64
#define NB256 ((MAXN + 255) / 256)
#define PQBLK 391     // ceil(50000/128)
#define HBLK  800
#define SSBLK 592     // scan+scatter fused grid

// ---- device scratch ----
__device__ float2  g_WAB[HD * XD];          // interleaved {A[j][r], B[j][r]}
__device__ float   g_c[HD];
__device__ __half2 g_ph[MAXN * (HD / 2)];   // p (c folded) in half2
__device__ __half2 g_qh[MAXN * (HD / 2)];   // q in half2
__device__ float   g_Z[MAXN * HD];          // relu-sum accumulator
__device__ int     g_deg[MAXN];
__device__ int     g_off[MAXN + 1];
__device__ int     g_rank[MAXE];
__device__ int     g_srcs[MAXE];
__device__ int     g_bsum[NB256];
__device__ int     g_is64;
__device__ int     g_scount = 0;
__device__ volatile int g_sgen = 0;

// ---- f32x2 packed helpers (sm_103a) ----
__device__ __forceinline__ unsigned long long pack2(float lo, float hi) {
    unsigned long long d;
    asm("mov.b64 %0, {%1, %2};" : "=l"(d) : "f"(lo), "f"(hi));
    return d;
}
__device__ __forceinline__ void unpack2(float& lo, float& hi, unsigned long long v) {
    asm("mov.b64 {%0, %1}, %2;" : "=f"(lo), "=f"(hi) : "l"(v));
}
__device__ __forceinline__ unsigned long long fma2(unsigned long long a,
                                                   unsigned long long b,
                                                   unsigned long long c) {
    unsigned long long d;
    asm("fma.rn.f32x2 %0, %1, %2, %3;" : "=l"(d) : "l"(a), "l"(b), "l"(c));
    return d;
}

__device__ __forceinline__ int load_idx(const void* ei, int i) {
    if (g_is64) return (int)((const long long*)ei)[i];
    return ((const int*)ei)[i];
}

__device__ __forceinline__ int warp_reduce(int v) {
#pragma unroll
    for (int o = 16; o > 0; o >>= 1) v += __shfl_down_sync(0xffffffffu, v, o);
    return v;
}

// ---- init: zero deg; block 0 detects dtype + builds WAB/c ----
__global__ void init_kernel(const float* __restrict__ W1,
                            const float* __restrict__ b1,
                            const float* __restrict__ scalars,
                            const int* __restrict__ ei32, int n) {
    int i = blockIdx.x * blockDim.x + threadIdx.x;
    if (i < n) g_deg[i] = 0;
    if (blockIdx.x == 0) {
        __shared__ int s_any;
        if (threadIdx.x == 0) s_any = 0;
        __syncthreads();
        for (int k = threadIdx.x; k < 1024; k += blockDim.x)
            if (ei32[2 * k + 1] != 0) s_any = 1;
        __syncthreads();
        if (threadIdx.x == 0) g_is64 = (s_any == 0) ? 1 : 0;
        int j = threadIdx.x;
        if (j < HD) {
            float c = b1[j];
#pragma unroll
            for (int s = 0; s < 16; s++) c += scalars[s] * W1[(32 + s) * HD + j];
            g_c[j] = c;
#pragma unroll
            for (int r = 0; r < XD; r++) {
                float wB = W1[(48 + r) * HD + j];
                g_WAB[j * XD + r] = make_float2(W1[r * HD + j] - wB, wB);
            }
        }
    }
}

// ---- fused: pq (f32x2, thread-per-node, fp16 outputs) + hist ----
__global__ void __launch_bounds__(128)
pqhist_kernel(const float* __restrict__ x, const void* __restrict__ ei,
              int n, int e) {
    __shared__ float2 sWAB[HD * XD];      // 24KB
    __shared__ float  sc[HD];
    __shared__ float  xs[128][XD + 1];
    const int tid = threadIdx.x;

    if (blockIdx.x < PQBLK) {
        for (int i = tid; i < HD * XD; i += 128) sWAB[i] = g_WAB[i];
        if (tid < HD) sc[tid] = g_c[tid];
        const int base = blockIdx.x * 128;
        const int cnt = min(128, n - base);
        for (int i = tid; i < cnt * XD; i += 128)
            xs[i >> 5][i & 31] = x[(size_t)base * XD + i];
        __syncthreads();

        const int node = base + tid;
        if (tid < cnt) {
            float xr[XD];
#pragma unroll
            for (int r = 0; r < XD; r++) xr[r] = xs[tid][r];

#pragma unroll 1
            for (int jc = 0; jc < 12; jc++) {
                unsigned long long acc[8];
#pragma unroll
                for (int u = 0; u < 8; u++) acc[u] = pack2(sc[jc * 8 + u], 0.0f);
#pragma unroll
                for (int r2 = 0; r2 < 16; r2++) {
                    unsigned long long xx0 = pack2(xr[2 * r2], xr[2 * r2]);
                    unsigned long long xx1 = pack2(xr[2 * r2 + 1], xr[2 * r2 + 1]);
#pragma unroll
                    for (int u = 0; u < 8; u++) {
                        ulonglong2 wv = *(const ulonglong2*)&sWAB[(jc * 8 + u) * XD + 2 * r2];
                        acc[u] = fma2(xx0, wv.x, acc[u]);
                        acc[u] = fma2(xx1, wv.y, acc[u]);
                    }
                }
                float pa[8], qa[8];
#pragma unroll
                for (int u = 0; u < 8; u++) unpack2(pa[u], qa[u], acc[u]);
                __half2 hp[4], hq[4];
#pragma unroll
                for (int u = 0; u < 4; u++) {
                    hp[u] = __floats2half2_rn(pa[2 * u], pa[2 * u + 1]);
                    hq[u] = __floats2half2_rn(qa[2 * u], qa[2 * u + 1]);
                }
                ((uint4*)g_ph)[(size_t)node * 12 + jc] = *(uint4*)hp;
                ((uint4*)g_qh)[(size_t)node * 12 + jc] = *(uint4*)hq;
            }
        }
    } else {
        const int hb = blockIdx.x - PQBLK;
        for (int i = hb * 128 + tid; i < e; i += HBLK * 128) {
            int dst = load_idx(ei, e + i);
            g_rank[i] = atomicAdd(&g_deg[dst], 1);
        }
    }
}

// ---- fused scan (first nb blocks) + scatter (all blocks) ----
__global__ void __launch_bounds__(256)
scanscatter_kernel(const void* __restrict__ ei, int n, int e, int nb) {
    __shared__ int wsum[8];
    __shared__ int wpre[8];
    __shared__ int sbase;
    const int tid = threadIdx.x;
    const int lane = tid & 31, wid = tid >> 5;
    const int b = blockIdx.x;
    const int i = b * 256 + tid;
    const int v = (b < nb && i < n) ? g_deg[i] : 0;

    if (b < nb) {
        int s = warp_reduce(v);
        if (lane == 0) wsum[wid] = s;
        __syncthreads();
        if (tid < 8) {
            int t = wsum[tid];
#pragma unroll
            for (int o = 4; o > 0; o >>= 1) t += __shfl_down_sync(0xffu, t, o);
            if (tid == 0) g_bsum[b] = t;
        }
    }
    // grid barrier 1
    __syncthreads();
    if (tid == 0) {
        __threadfence();
        int gen = g_sgen;
        if (atomicAdd(&g_scount, 1) == SSBLK - 1) {
            g_scount = 0;
            __threadfence();
            g_sgen = gen + 1;
        } else {
            while (g_sgen == gen) { __nanosleep(32); }
        }
        __threadfence();
    }
    __syncthreads();

    if (b < nb) {
        if (tid < 32) {
            int ss = 0;
            for (int k = tid; k < b; k += 32) ss += g_bsum[k];
            ss = warp_reduce(ss);
            if (tid == 0) sbase = ss;
        }
        int incl = v;
#pragma unroll
        for (int o = 1; o < 32; o <<= 1) {
            int t = __shfl_up_sync(0xffffffffu, incl, o);
            if (lane >= o) incl += t;
        }
        if (lane == 31) wpre[wid] = incl;
        __syncthreads();
        if (tid == 0) {
            int run = 0;
#pragma unroll
            for (int k = 0; k < 8; k++) { int t = wpre[k]; wpre[k] = run; run += t; }
        }
        __syncthreads();
        if (i < n) {
            int excl = sbase + wpre[wid] + incl - v;
            g_off[i] = excl;
            if (i == n - 1) g_off[n] = excl + v;
        }
    }
    // grid barrier 2
    __syncthreads();
    if (tid == 0) {
        __threadfence();
        int gen = g_sgen;
        if (atomicAdd(&g_scount, 1) == SSBLK - 1) {
            g_scount = 0;
            __threadfence();
            g_sgen = gen + 1;
        } else {
            while (g_sgen == gen) { __nanosleep(32); }
        }
        __threadfence();
    }
    __syncthreads();

    for (int k = b * 256 + tid; k < e; k += SSBLK * 256) {
        int src = load_idx(ei, k);
        int dst = load_idx(ei, e + k);
        g_srcs[g_off[dst] + g_rank[k]] = src;
    }
}

// ---- gather: warp per 2 adjacent nodes (contiguous edge range) ----
__global__ void __launch_bounds__(256)
gather_kernel(int n) {
    const int w = threadIdx.x >> 5, lane = threadIdx.x & 31;
    const int nA = (blockIdx.x * 8 + w) * 2;
    if (nA >= n) return;
    const bool hasB = (nA + 1) < n;

    const int s0 = __ldg(&g_off[nA]);
    const int s1 = __ldg(&g_off[nA + 1]);
    const int s2 = hasB ? __ldg(&g_off[nA + 2]) : s1;

    const uint2 zero2 = make_uint2(0u, 0u);
    uint2 pA2 = (lane < 24) ? __ldg((const uint2*)(g_ph + (size_t)nA * 48) + lane) : zero2;
    uint2 pB2 = (hasB && lane < 24)
              ? __ldg((const uint2*)(g_ph + (size_t)(nA + 1) * 48) + lane) : zero2;
    const __half2 pA0 = *(__half2*)&pA2.x, pA1 = *(__half2*)&pA2.y;
    const __half2 pB0 = *(__half2*)&pB2.x, pB1 = *(__half2*)&pB2.y;
    const __half2 hz = __float2half2_rn(0.f);

    float zAx = 0.f, zAy = 0.f, zAz = 0.f, zAw = 0.f;
    float zBx = 0.f, zBy = 0.f, zBz = 0.f, zBw = 0.f;

    for (int base = s0; base < s2; base += 32) {
        const int cnt = min(32, s2 - base);
        const int split = min(max(s1 - base, 0), cnt);   // edges < split belong to A
        int sreg = (lane < cnt) ? __ldg(&g_srcs[base + lane]) : 0;
        int k = 0;
        for (; k + 7 < cnt; k += 8) {
            uint2 v[8];
#pragma unroll
            for (int u = 0; u < 8; u++) {
                int su = __shfl_sync(0xffffffffu, sreg, k + u);
                v[u] = (lane < 24)
                     ? __ldg((const uint2*)(g_qh + (size_t)su * 48) + lane)
                     : zero2;
            }
#pragma unroll
            for (int u = 0; u < 8; u++) {
                const bool isA = (k + u) < split;
                const __half2 pp0 = isA ? pA0 : pB0;
                const __half2 pp1 = isA ? pA1 : pB1;
                __half2 h0 = __hmax2(__hadd2(pp0, *(__half2*)&v[u].x), hz);
                __half2 h1 = __hmax2(__hadd2(pp1, *(__half2*)&v[u].y), hz);
                float2 f0 = __half22float2(h0);
                float2 f1 = __half22float2(h1);
                if (isA) { zAx += f0.x; zAy += f0.y; zAz += f1.x; zAw += f1.y; }
                else     { zBx += f0.x; zBy += f0.y; zBz += f1.x; zBw += f1.y; }
            }
        }
        for (; k < cnt; k++) {
            int su = __shfl_sync(0xffffffffu, sreg, k);
            uint2 v0 = (lane < 24)
                     ? __ldg((const uint2*)(g_qh + (size_t)su * 48) + lane)
                     : zero2;
            const bool isA = k < split;
            const __half2 pp0 = isA ? pA0 : pB0;
            const __half2 pp1 = isA ? pA1 : pB1;
            __half2 h0 = __hmax2(__hadd2(pp0, *(__half2*)&v0.x), hz);
            __half2 h1 = __hmax2(__hadd2(pp1, *(__half2*)&v0.y), hz);
            float2 f0 = __half22float2(h0);
            float2 f1 = __half22float2(h1);
            if (isA) { zAx += f0.x; zAy += f0.y; zAz += f1.x; zAw += f1.y; }
            else     { zBx += f0.x; zBy += f0.y; zBz += f1.x; zBw += f1.y; }
        }
    }
    if (lane < 24) {
        *(float4*)(g_Z + (size_t)nA * HD + lane * 4) = make_float4(zAx, zAy, zAz, zAw);
        if (hasB)
            *(float4*)(g_Z + (size_t)(nA + 1) * HD + lane * 4) = make_float4(zBx, zBy, zBz, zBw);
    }
}

// ---- gemm: out = Z @ W2 + deg*b2, dup-broadcast z, f32x2 fma ----
__global__ void __launch_bounds__(256)
gemm_kernel(const float* __restrict__ W2, const float* __restrict__ b2,
            float* __restrict__ out, int n) {
    __shared__ unsigned long long sW2v[HD * 32];        // {W2[k][c], W2[k][c+32]}
    __shared__ unsigned long long sdup[32][HD];         // {z, z} per node/k
    __shared__ float sb2[OD];
    const int tid = threadIdx.x;
    for (int i = tid; i < HD * 32; i += 256) {
        int k = i >> 5, c = i & 31;
        sW2v[i] = pack2(W2[k * OD + c], W2[k * OD + c + 32]);
    }
    if (tid < OD) sb2[tid] = b2[tid];

    const int base = blockIdx.x * 32;
    for (int i = tid; i < 32 * HD; i += 256) {
        int nl = i / HD, k = i % HD;
        int node = base + nl;
        float z = (node < n) ? g_Z[(size_t)node * HD + k] : 0.f;
        sdup[nl][k] = pack2(z, z);
    }
    __syncthreads();

    const int w = tid >> 5, lane = tid & 31;
    const int nd0 = w * 4;
    unsigned long long acc[4];
#pragma unroll
    for (int nd = 0; nd < 4; nd++) {
        int node = base + nd0 + nd;
        int deg = 0;
        if (node < n) deg = __ldg(&g_off[node + 1]) - __ldg(&g_off[node]);
        acc[nd] = pack2((float)deg * sb2[lane], (float)deg * sb2[lane + 32]);
    }

#pragma unroll 8
    for (int k = 0; k < HD; k++) {
        unsigned long long wp = sW2v[k * 32 + lane];
        acc[0] = fma2(sdup[nd0 + 0][k], wp, acc[0]);
        acc[1] = fma2(sdup[nd0 + 1][k], wp, acc[1]);
        acc[2] = fma2(sdup[nd0 + 2][k], wp, acc[2]);
        acc[3] = fma2(sdup[nd0 + 3][k], wp, acc[3]);
    }

#pragma unroll
    for (int nd = 0; nd < 4; nd++) {
        int node = base + nd0 + nd;
        if (node < n) {
            float a0, a1;
            unpack2(a0, a1, acc[nd]);
            out[(size_t)node * OD + lane] = a0;
            out[(size_t)node * OD + lane + 32] = a1;
        }
    }
}

extern "C" void kernel_launch(void* const* d_in, const int* in_sizes, int n_in,
                              void* d_out, int out_size) {
    const float* x       = (const float*)d_in[0];
    const float* scalars = (const float*)d_in[1];
    const float* W1      = (const float*)d_in[2];
    const float* b1      = (const float*)d_in[3];
    const float* W2      = (const float*)d_in[4];
    const float* b2      = (const float*)d_in[5];
    const void*  ei      = d_in[6];
    float* out = (float*)d_out;

    int n = in_sizes[0] / XD;   // 50000
    int e = in_sizes[6] / 2;    // 800000
    int nb = (n + 255) / 256;   // 196

    init_kernel<<<nb, 256>>>(W1, b1, scalars, (const int*)ei, n);
    pqhist_kernel<<<PQBLK + HBLK, 128>>>(x, ei, n, e);
    scanscatter_kernel<<<SSBLK, 256>>>(ei, n, e, nb);
    gather_kernel<<<(n + 15) / 16, 256>>>(n);        // profile slot 4
    gemm_kernel<<<(n + 31) / 32, 256>>>(W2, b2, out, n);
}

// round 12
// speedup vs baseline: 1.0855x; 1.0855x over previous
#include <cuda_runtime.h>
#include <cuda_fp16.h>
#include <stdint.h>

#define MAXN 50000
#define MAXE 800000
#define XD 32
#define HD 96
#define OD 64
#define NB256 ((MAXN + 255) / 256)
#define PQBLK 391     // ceil(50000/128)
#define HBLK  800

// ---- device scratch ----
__device__ float2  g_WAB[HD * XD];          // interleaved {A[j][r], B[j][r]}
__device__ float   g_c[HD];
__device__ __half2 g_ph[MAXN * (HD / 2)];   // p (c folded) in half2
__device__ __half2 g_qh[MAXN * (HD / 2)];   // q in half2
__device__ float   g_Z[MAXN * HD];          // relu-sum accumulator
__device__ int     g_deg[MAXN];
__device__ int     g_off[MAXN + 1];
__device__ int     g_rank[MAXE];
__device__ int     g_srcs[MAXE];
__device__ int     g_bsum[NB256];
__device__ int     g_is64;
__device__ int     g_scount = 0;
__device__ volatile int g_sgen = 0;

// ---- f32x2 packed helpers (sm_103a) ----
__device__ __forceinline__ unsigned long long pack2(float lo, float hi) {
    unsigned long long d;
    asm("mov.b64 %0, {%1, %2};" : "=l"(d) : "f"(lo), "f"(hi));
    return d;
}
__device__ __forceinline__ void unpack2(float& lo, float& hi, unsigned long long v) {
    asm("mov.b64 {%0, %1}, %2;" : "=f"(lo), "=f"(hi) : "l"(v));
}
__device__ __forceinline__ unsigned long long fma2(unsigned long long a,
                                                   unsigned long long b,
                                                   unsigned long long c) {
    unsigned long long d;
    asm("fma.rn.f32x2 %0, %1, %2, %3;" : "=l"(d) : "l"(a), "l"(b), "l"(c));
    return d;
}

__device__ __forceinline__ int load_idx(const void* ei, int i) {
    if (g_is64) return (int)((const long long*)ei)[i];
    return ((const int*)ei)[i];
}

__device__ __forceinline__ int warp_reduce(int v) {
#pragma unroll
    for (int o = 16; o > 0; o >>= 1) v += __shfl_down_sync(0xffffffffu, v, o);
    return v;
}

// ---- init: zero deg; block 0 detects dtype + builds WAB/c ----
__global__ void init_kernel(const float* __restrict__ W1,
                            const float* __restrict__ b1,
                            const float* __restrict__ scalars,
                            const int* __restrict__ ei32, int n) {
    int i = blockIdx.x * blockDim.x + threadIdx.x;
    if (i < n) g_deg[i] = 0;
    if (blockIdx.x == 0) {
        __shared__ int s_any;
        if (threadIdx.x == 0) s_any = 0;
        __syncthreads();
        for (int k = threadIdx.x; k < 1024; k += blockDim.x)
            if (ei32[2 * k + 1] != 0) s_any = 1;
        __syncthreads();
        if (threadIdx.x == 0) g_is64 = (s_any == 0) ? 1 : 0;
        int j = threadIdx.x;
        if (j < HD) {
            float c = b1[j];
#pragma unroll
            for (int s = 0; s < 16; s++) c += scalars[s] * W1[(32 + s) * HD + j];
            g_c[j] = c;
#pragma unroll
            for (int r = 0; r < XD; r++) {
                float wB = W1[(48 + r) * HD + j];
                g_WAB[j * XD + r] = make_float2(W1[r * HD + j] - wB, wB);
            }
        }
    }
}

// ---- fused: pq (f32x2, thread-per-node, fp16 outputs) + hist ----
__global__ void __launch_bounds__(128)
pqhist_kernel(const float* __restrict__ x, const void* __restrict__ ei,
              int n, int e) {
    __shared__ float2 sWAB[HD * XD];      // 24KB
    __shared__ float  sc[HD];
    __shared__ float  xs[128][XD + 1];
    const int tid = threadIdx.x;

    if (blockIdx.x < PQBLK) {
        for (int i = tid; i < HD * XD; i += 128) sWAB[i] = g_WAB[i];
        if (tid < HD) sc[tid] = g_c[tid];
        const int base = blockIdx.x * 128;
        const int cnt = min(128, n - base);
        for (int i = tid; i < cnt * XD; i += 128)
            xs[i >> 5][i & 31] = x[(size_t)base * XD + i];
        __syncthreads();

        const int node = base + tid;
        if (tid < cnt) {
            float xr[XD];
#pragma unroll
            for (int r = 0; r < XD; r++) xr[r] = xs[tid][r];

#pragma unroll 1
            for (int jc = 0; jc < 12; jc++) {
                unsigned long long acc[8];
#pragma unroll
                for (int u = 0; u < 8; u++) acc[u] = pack2(sc[jc * 8 + u], 0.0f);
#pragma unroll
                for (int r2 = 0; r2 < 16; r2++) {
                    unsigned long long xx0 = pack2(xr[2 * r2], xr[2 * r2]);
                    unsigned long long xx1 = pack2(xr[2 * r2 + 1], xr[2 * r2 + 1]);
#pragma unroll
                    for (int u = 0; u < 8; u++) {
                        ulonglong2 wv = *(const ulonglong2*)&sWAB[(jc * 8 + u) * XD + 2 * r2];
                        acc[u] = fma2(xx0, wv.x, acc[u]);
                        acc[u] = fma2(xx1, wv.y, acc[u]);
                    }
                }
                float pa[8], qa[8];
#pragma unroll
                for (int u = 0; u < 8; u++) unpack2(pa[u], qa[u], acc[u]);
                __half2 hp[4], hq[4];
#pragma unroll
                for (int u = 0; u < 4; u++) {
                    hp[u] = __floats2half2_rn(pa[2 * u], pa[2 * u + 1]);
                    hq[u] = __floats2half2_rn(qa[2 * u], qa[2 * u + 1]);
                }
                ((uint4*)g_ph)[(size_t)node * 12 + jc] = *(uint4*)hp;
                ((uint4*)g_qh)[(size_t)node * 12 + jc] = *(uint4*)hq;
            }
        }
    } else {
        const int hb = blockIdx.x - PQBLK;
        for (int i = hb * 128 + tid; i < e; i += HBLK * 128) {
            int dst = load_idx(ei, e + i);
            g_rank[i] = atomicAdd(&g_deg[dst], 1);
        }
    }
}

// ---- merged scan: block sums -> grid barrier -> offsets ----
__global__ void scan_kernel(int n, int nb) {
    __shared__ int wsum[8];
    __shared__ int wpre[8];
    __shared__ int sbase;
    const int tid = threadIdx.x;
    const int lane = tid & 31, wid = tid >> 5;
    const int b = blockIdx.x;
    const int i = b * 256 + tid;
    const int v = (i < n) ? g_deg[i] : 0;

    int s = warp_reduce(v);
    if (lane == 0) wsum[wid] = s;
    __syncthreads();
    if (tid < 8) {
        int t = wsum[tid];
#pragma unroll
        for (int o = 4; o > 0; o >>= 1) t += __shfl_down_sync(0xffu, t, o);
        if (tid == 0) g_bsum[b] = t;
    }
    __syncthreads();
    if (tid == 0) {
        __threadfence();
        int gen = g_sgen;
        if (atomicAdd(&g_scount, 1) == nb - 1) {
            g_scount = 0;
            __threadfence();
            g_sgen = gen + 1;
        } else {
            while (g_sgen == gen) { __nanosleep(32); }
        }
        __threadfence();
    }
    __syncthreads();

    if (tid < 32) {
        int ss = 0;
        for (int k = tid; k < b; k += 32) ss += g_bsum[k];
        ss = warp_reduce(ss);
        if (tid == 0) sbase = ss;
    }
    int incl = v;
#pragma unroll
    for (int o = 1; o < 32; o <<= 1) {
        int t = __shfl_up_sync(0xffffffffu, incl, o);
        if (lane >= o) incl += t;
    }
    if (lane == 31) wpre[wid] = incl;
    __syncthreads();
    if (tid == 0) {
        int run = 0;
#pragma unroll
        for (int k = 0; k < 8; k++) { int t = wpre[k]; wpre[k] = run; run += t; }
    }
    __syncthreads();
    if (i < n) {
        int excl = sbase + wpre[wid] + incl - v;
        g_off[i] = excl;
        if (i == n - 1) g_off[n] = excl + v;
    }
}

// ---- deterministic scatter ----
__global__ void scatter_kernel(const void* __restrict__ ei, int e) {
    int i = blockIdx.x * blockDim.x + threadIdx.x;
    if (i >= e) return;
    int src = load_idx(ei, i);
    int dst = load_idx(ei, e + i);
    g_srcs[g_off[dst] + g_rank[i]] = src;
}

// ---- gather: warp-per-node, batch-2 fp16 pair reduction ----
__global__ void __launch_bounds__(256, 6)
gather_kernel(int n) {
    const int w = threadIdx.x >> 5, lane = threadIdx.x & 31;
    const int node = blockIdx.x * 8 + w;
    if (node >= n) return;

    const int off0 = __ldg(&g_off[node]);
    const int off1 = __ldg(&g_off[node + 1]);
    const uint2 zero2 = make_uint2(0u, 0u);
    uint2 pp2 = (lane < 24)
              ? __ldg((const uint2*)(g_ph + (size_t)node * 48) + lane)
              : zero2;
    const __half2 pph0 = *(__half2*)&pp2.x;
    const __half2 pph1 = *(__half2*)&pp2.y;
    const __half2 hz = __float2half2_rn(0.f);
    float zx = 0.f, zy = 0.f, zz = 0.f, zw = 0.f;

    for (int bb = off0; bb < off1; bb += 32) {
        int cnt = min(32, off1 - bb);
        int sreg = (lane < cnt) ? __ldg(&g_srcs[bb + lane]) : 0;
        int k = 0;
        for (; k + 7 < cnt; k += 8) {
            uint2 v[8];
#pragma unroll
            for (int u = 0; u < 8; u++) {
                int su = __shfl_sync(0xffffffffu, sreg, k + u);
                v[u] = (lane < 24)
                     ? __ldg((const uint2*)(g_qh + (size_t)su * 48) + lane)
                     : zero2;
            }
#pragma unroll
            for (int u = 0; u < 8; u += 2) {
                // relu both edges in fp16, pair-sum, convert once
                __half2 a0 = __hmax2(__hadd2(pph0, *(__half2*)&v[u].x), hz);
                __half2 a1 = __hmax2(__hadd2(pph1, *(__half2*)&v[u].y), hz);
                __half2 b0 = __hmax2(__hadd2(pph0, *(__half2*)&v[u + 1].x), hz);
                __half2 b1 = __hmax2(__hadd2(pph1, *(__half2*)&v[u + 1].y), hz);
                __half2 s0 = __hadd2(a0, b0);
                __half2 s1 = __hadd2(a1, b1);
                float2 f0 = __half22float2(s0);
                float2 f1 = __half22float2(s1);
                zx += f0.x; zy += f0.y; zz += f1.x; zw += f1.y;
            }
        }
        for (; k < cnt; k++) {
            int su = __shfl_sync(0xffffffffu, sreg, k);
            uint2 v0 = (lane < 24)
                     ? __ldg((const uint2*)(g_qh + (size_t)su * 48) + lane)
                     : zero2;
            __half2 h0 = __hmax2(__hadd2(pph0, *(__half2*)&v0.x), hz);
            __half2 h1 = __hmax2(__hadd2(pph1, *(__half2*)&v0.y), hz);
            float2 f0 = __half22float2(h0);
            float2 f1 = __half22float2(h1);
            zx += f0.x; zy += f0.y; zz += f1.x; zw += f1.y;
        }
    }
    if (lane < 24)
        *(float4*)(g_Z + (size_t)node * HD + lane * 4) = make_float4(zx, zy, zz, zw);
}

// ---- gemm: out = Z @ W2 + deg*b2, dup-broadcast z, f32x2 fma ----
__global__ void __launch_bounds__(256)
gemm_kernel(const float* __restrict__ W2, const float* __restrict__ b2,
            float* __restrict__ out, int n) {
    __shared__ unsigned long long sW2v[HD * 32];        // {W2[k][c], W2[k][c+32]}
    __shared__ unsigned long long sdup[32][HD];         // {z, z} per node/k
    __shared__ float sb2[OD];
    const int tid = threadIdx.x;
    for (int i = tid; i < HD * 32; i += 256) {
        int k = i >> 5, c = i & 31;
        sW2v[i] = pack2(W2[k * OD + c], W2[k * OD + c + 32]);
    }
    if (tid < OD) sb2[tid] = b2[tid];

    const int base = blockIdx.x * 32;
    for (int i = tid; i < 32 * HD; i += 256) {
        int nl = i / HD, k = i % HD;
        int node = base + nl;
        float z = (node < n) ? g_Z[(size_t)node * HD + k] : 0.f;
        sdup[nl][k] = pack2(z, z);
    }
    __syncthreads();

    const int w = tid >> 5, lane = tid & 31;
    const int nd0 = w * 4;
    unsigned long long acc[4];
#pragma unroll
    for (int nd = 0; nd < 4; nd++) {
        int node = base + nd0 + nd;
        int deg = 0;
        if (node < n) deg = __ldg(&g_off[node + 1]) - __ldg(&g_off[node]);
        acc[nd] = pack2((float)deg * sb2[lane], (float)deg * sb2[lane + 32]);
    }

#pragma unroll 8
    for (int k = 0; k < HD; k++) {
        unsigned long long wp = sW2v[k * 32 + lane];
        acc[0] = fma2(sdup[nd0 + 0][k], wp, acc[0]);
        acc[1] = fma2(sdup[nd0 + 1][k], wp, acc[1]);
        acc[2] = fma2(sdup[nd0 + 2][k], wp, acc[2]);
        acc[3] = fma2(sdup[nd0 + 3][k], wp, acc[3]);
    }

#pragma unroll
    for (int nd = 0; nd < 4; nd++) {
        int node = base + nd0 + nd;
        if (node < n) {
            float a0, a1;
            unpack2(a0, a1, acc[nd]);
            out[(size_t)node * OD + lane] = a0;
            out[(size_t)node * OD + lane + 32] = a1;
        }
    }
}

extern "C" void kernel_launch(void* const* d_in, const int* in_sizes, int n_in,
                              void* d_out, int out_size) {
    const float* x       = (const float*)d_in[0];
    const float* scalars = (const float*)d_in[1];
    const float* W1      = (const float*)d_in[2];
    const float* b1      = (const float*)d_in[3];
    const float* W2      = (const float*)d_in[4];
    const float* b2      = (const float*)d_in[5];
    const void*  ei      = d_in[6];
    float* out = (float*)d_out;

    int n = in_sizes[0] / XD;   // 50000
    int e = in_sizes[6] / 2;    // 800000
    int nb = (n + 255) / 256;   // 196

    init_kernel<<<nb, 256>>>(W1, b1, scalars, (const int*)ei, n);
    pqhist_kernel<<<PQBLK + HBLK, 128>>>(x, ei, n, e);
    scan_kernel<<<nb, 256>>>(n, nb);
    scatter_kernel<<<(e + 255) / 256, 256>>>(ei, e);
    gather_kernel<<<(n + 7) / 8, 256>>>(n);
    gemm_kernel<<<(n + 31) / 32, 256>>>(W2, b2, out, n);
}

// round 13
// speedup vs baseline: 1.1033x; 1.0164x over previous
#include <cuda_runtime.h>
#include <cuda_fp16.h>
#include <stdint.h>

#define MAXN 50000
#define MAXE 800000
#define XD 32
#define HD 96
#define OD 64
#define PQBLK 391                 // ceil(50000/128) pq blocks
#define HBLK  645                 // edge-chain blocks (barrier participants)
#define TOTBLK (PQBLK + HBLK)     // 1036 = 7 * 148
#define NSCAN 391                 // ceil(50000/128) scan chunks

// ---- device scratch ----
__device__ __half2 g_ph[MAXN * (HD / 2)];   // p (c folded) in half2
__device__ __half2 g_qh[MAXN * (HD / 2)];   // q in half2
__device__ float   g_Z[MAXN * HD];          // relu-sum accumulator
__device__ int     g_deg[MAXN];
__device__ int     g_off[MAXN + 1];
__device__ int     g_rank[MAXE];
__device__ int     g_srcs[MAXE];
__device__ int     g_bsum[NSCAN];
__device__ int     g_scount = 0;
__device__ volatile int g_sgen = 0;

// ---- f32x2 packed helpers (sm_103a) ----
__device__ __forceinline__ unsigned long long pack2(float lo, float hi) {
    unsigned long long d;
    asm("mov.b64 %0, {%1, %2};" : "=l"(d) : "f"(lo), "f"(hi));
    return d;
}
__device__ __forceinline__ void unpack2(float& lo, float& hi, unsigned long long v) {
    asm("mov.b64 {%0, %1}, %2;" : "=f"(lo), "=f"(hi) : "l"(v));
}
__device__ __forceinline__ unsigned long long fma2(unsigned long long a,
                                                   unsigned long long b,
                                                   unsigned long long c) {
    unsigned long long d;
    asm("fma.rn.f32x2 %0, %1, %2, %3;" : "=l"(d) : "l"(a), "l"(b), "l"(c));
    return d;
}

__device__ __forceinline__ int warp_reduce(int v) {
#pragma unroll
    for (int o = 16; o > 0; o >>= 1) v += __shfl_down_sync(0xffffffffu, v, o);
    return v;
}

// barrier among the HBLK edge-chain blocks only
__device__ __forceinline__ void hist_barrier() {
    __syncthreads();
    if (threadIdx.x == 0) {
        __threadfence();
        int gen = g_sgen;
        if (atomicAdd(&g_scount, 1) == HBLK - 1) {
            g_scount = 0;
            __threadfence();
            g_sgen = gen + 1;
        } else {
            while (g_sgen == gen) { __nanosleep(32); }
        }
        __threadfence();
    }
    __syncthreads();
}

// ---- megafused front end: pq (blocks < PQBLK) || zero->hist->scan->scatter ----
__global__ void __launch_bounds__(128, 7)
mega_kernel(const float* __restrict__ x, const float* __restrict__ scalars,
            const float* __restrict__ W1, const float* __restrict__ b1,
            const void* __restrict__ ei, int n, int e) {
    __shared__ float2 sWAB[HD * XD];    // 24KB (pq blocks only)
    __shared__ float  sc[HD];
    __shared__ int    s_any;
    __shared__ int    wpre[4];
    __shared__ int    sbase;
    const int tid = threadIdx.x;
    const int bid = blockIdx.x;

    if (bid < PQBLK) {
        // --- build A/B/c in smem straight from W1/b1/scalars ---
        for (int i = tid; i < HD * XD; i += 128) {
            int j = i >> 5, r = i & 31;
            float wB = W1[(48 + r) * HD + j];
            sWAB[i] = make_float2(W1[r * HD + j] - wB, wB);   // index j*XD+r == i
        }
        if (tid < HD) {
            float c = b1[tid];
#pragma unroll
            for (int s = 0; s < 16; s++) c += scalars[s] * W1[(32 + s) * HD + tid];
            sc[tid] = c;
        }
        __syncthreads();

        const int node = bid * 128 + tid;
        if (node < n) {
            float xr[XD];
            const float4* xp = (const float4*)(x + (size_t)node * XD);
#pragma unroll
            for (int i = 0; i < 8; i++) {
                float4 v = __ldg(&xp[i]);
                xr[4 * i] = v.x; xr[4 * i + 1] = v.y;
                xr[4 * i + 2] = v.z; xr[4 * i + 3] = v.w;
            }
#pragma unroll 1
            for (int jc = 0; jc < 12; jc++) {
                unsigned long long acc[8];
#pragma unroll
                for (int u = 0; u < 8; u++) acc[u] = pack2(sc[jc * 8 + u], 0.0f);
#pragma unroll
                for (int r2 = 0; r2 < 16; r2++) {
                    unsigned long long xx0 = pack2(xr[2 * r2], xr[2 * r2]);
                    unsigned long long xx1 = pack2(xr[2 * r2 + 1], xr[2 * r2 + 1]);
#pragma unroll
                    for (int u = 0; u < 8; u++) {
                        ulonglong2 wv = *(const ulonglong2*)&sWAB[(jc * 8 + u) * XD + 2 * r2];
                        acc[u] = fma2(xx0, wv.x, acc[u]);
                        acc[u] = fma2(xx1, wv.y, acc[u]);
                    }
                }
                float pa[8], qa[8];
#pragma unroll
                for (int u = 0; u < 8; u++) unpack2(pa[u], qa[u], acc[u]);
                __half2 hp[4], hq[4];
#pragma unroll
                for (int u = 0; u < 4; u++) {
                    hp[u] = __floats2half2_rn(pa[2 * u], pa[2 * u + 1]);
                    hq[u] = __floats2half2_rn(qa[2 * u], qa[2 * u + 1]);
                }
                ((uint4*)g_ph)[(size_t)node * 12 + jc] = *(uint4*)hp;
                ((uint4*)g_qh)[(size_t)node * 12 + jc] = *(uint4*)hq;
            }
        }
    } else {
        const int hb = bid - PQBLK;        // 0..HBLK-1
        const int lane = tid & 31, wid = tid >> 5;

        // --- zero deg + block-local dtype detect ---
        for (int i = hb * 128 + tid; i < n; i += HBLK * 128) g_deg[i] = 0;
        if (tid == 0) s_any = 0;
        __syncthreads();
        {
            const int* ei32 = (const int*)ei;
            int a = 0;
            for (int k = tid; k < 1024; k += 128) a |= ei32[2 * k + 1];
            if (a) s_any = 1;
        }
        __syncthreads();
        const bool is64 = (s_any == 0);
        const long long* p64 = (const long long*)ei;
        const int* p32 = (const int*)ei;

        hist_barrier();   // deg zeroed everywhere

        // --- hist + rank ---
        for (int i = hb * 128 + tid; i < e; i += HBLK * 128) {
            int dst = is64 ? (int)p64[e + i] : p32[e + i];
            g_rank[i] = atomicAdd(&g_deg[dst], 1);
        }
        hist_barrier();   // all counts done

        // --- scan pass 1: block-local scan of 128 deg entries ---
        const int i0 = hb * 128 + tid;
        int v = 0, excl_local = 0;
        if (hb < NSCAN) {
            v = (i0 < n) ? g_deg[i0] : 0;
            int incl = v;
#pragma unroll
            for (int o = 1; o < 32; o <<= 1) {
                int t = __shfl_up_sync(0xffffffffu, incl, o);
                if (lane >= o) incl += t;
            }
            if (lane == 31) wpre[wid] = incl;
            __syncthreads();
            if (tid == 0) {
                int run = 0;
#pragma unroll
                for (int k = 0; k < 4; k++) { int t = wpre[k]; wpre[k] = run; run += t; }
                g_bsum[hb] = run;
            }
            __syncthreads();
            excl_local = wpre[wid] + incl - v;
        }
        hist_barrier();   // all bsum written

        // --- scan pass 2: global prefix + write offsets ---
        if (hb < NSCAN) {
            if (tid < 32) {
                int ss = 0;
                for (int k = tid; k < hb; k += 32) ss += g_bsum[k];
                ss = warp_reduce(ss);
                if (tid == 0) sbase = ss;
            }
            __syncthreads();
            if (i0 < n) {
                int excl = sbase + excl_local;
                g_off[i0] = excl;
                if (i0 == n - 1) g_off[n] = excl + v;
            }
        }
        hist_barrier();   // all offsets written

        // --- deterministic scatter ---
        for (int i = hb * 128 + tid; i < e; i += HBLK * 128) {
            int src, dst;
            if (is64) { src = (int)p64[i]; dst = (int)p64[e + i]; }
            else      { src = p32[i];      dst = p32[e + i]; }
            g_srcs[g_off[dst] + g_rank[i]] = src;
        }
    }
}

// ---- gather: warp-per-node, batch-2 fp16 pair reduction ----
__global__ void __launch_bounds__(256, 6)
gather_kernel(int n) {
    const int w = threadIdx.x >> 5, lane = threadIdx.x & 31;
    const int node = blockIdx.x * 8 + w;
    if (node >= n) return;

    const int off0 = __ldg(&g_off[node]);
    const int off1 = __ldg(&g_off[node + 1]);
    const uint2 zero2 = make_uint2(0u, 0u);
    uint2 pp2 = (lane < 24)
              ? __ldg((const uint2*)(g_ph + (size_t)node * 48) + lane)
              : zero2;
    const __half2 pph0 = *(__half2*)&pp2.x;
    const __half2 pph1 = *(__half2*)&pp2.y;
    const __half2 hz = __float2half2_rn(0.f);
    float zx = 0.f, zy = 0.f, zz = 0.f, zw = 0.f;

    for (int bb = off0; bb < off1; bb += 32) {
        int cnt = min(32, off1 - bb);
        int sreg = (lane < cnt) ? __ldg(&g_srcs[bb + lane]) : 0;
        int k = 0;
        for (; k + 7 < cnt; k += 8) {
            uint2 v[8];
#pragma unroll
            for (int u = 0; u < 8; u++) {
                int su = __shfl_sync(0xffffffffu, sreg, k + u);
                v[u] = (lane < 24)
                     ? __ldg((const uint2*)(g_qh + (size_t)su * 48) + lane)
                     : zero2;
            }
#pragma unroll
            for (int u = 0; u < 8; u += 2) {
                __half2 a0 = __hmax2(__hadd2(pph0, *(__half2*)&v[u].x), hz);
                __half2 a1 = __hmax2(__hadd2(pph1, *(__half2*)&v[u].y), hz);
                __half2 b0 = __hmax2(__hadd2(pph0, *(__half2*)&v[u + 1].x), hz);
                __half2 b1 = __hmax2(__hadd2(pph1, *(__half2*)&v[u + 1].y), hz);
                __half2 s0 = __hadd2(a0, b0);
                __half2 s1 = __hadd2(a1, b1);
                float2 f0 = __half22float2(s0);
                float2 f1 = __half22float2(s1);
                zx += f0.x; zy += f0.y; zz += f1.x; zw += f1.y;
            }
        }
        for (; k < cnt; k++) {
            int su = __shfl_sync(0xffffffffu, sreg, k);
            uint2 v0 = (lane < 24)
                     ? __ldg((const uint2*)(g_qh + (size_t)su * 48) + lane)
                     : zero2;
            __half2 h0 = __hmax2(__hadd2(pph0, *(__half2*)&v0.x), hz);
            __half2 h1 = __hmax2(__hadd2(pph1, *(__half2*)&v0.y), hz);
            float2 f0 = __half22float2(h0);
            float2 f1 = __half22float2(h1);
            zx += f0.x; zy += f0.y; zz += f1.x; zw += f1.y;
        }
    }
    if (lane < 24)
        *(float4*)(g_Z + (size_t)node * HD + lane * 4) = make_float4(zx, zy, zz, zw);
}

// ---- gemm: out = Z @ W2 + deg*b2, dup-broadcast z, f32x2 fma ----
__global__ void __launch_bounds__(256)
gemm_kernel(const float* __restrict__ W2, const float* __restrict__ b2,
            float* __restrict__ out, int n) {
    __shared__ unsigned long long sW2v[HD * 32];        // {W2[k][c], W2[k][c+32]}
    __shared__ unsigned long long sdup[32][HD];         // {z, z} per node/k
    __shared__ float sb2[OD];
    const int tid = threadIdx.x;
    for (int i = tid; i < HD * 32; i += 256) {
        int k = i >> 5, c = i & 31;
        sW2v[i] = pack2(W2[k * OD + c], W2[k * OD + c + 32]);
    }
    if (tid < OD) sb2[tid] = b2[tid];

    const int base = blockIdx.x * 32;
    for (int i = tid; i < 32 * HD; i += 256) {
        int nl = i / HD, k = i % HD;
        int node = base + nl;
        float z = (node < n) ? g_Z[(size_t)node * HD + k] : 0.f;
        sdup[nl][k] = pack2(z, z);
    }
    __syncthreads();

    const int w = tid >> 5, lane = tid & 31;
    const int nd0 = w * 4;
    unsigned long long acc[4];
#pragma unroll
    for (int nd = 0; nd < 4; nd++) {
        int node = base + nd0 + nd;
        int deg = 0;
        if (node < n) deg = __ldg(&g_off[node + 1]) - __ldg(&g_off[node]);
        acc[nd] = pack2((float)deg * sb2[lane], (float)deg * sb2[lane + 32]);
    }

#pragma unroll 8
    for (int k = 0; k < HD; k++) {
        unsigned long long wp = sW2v[k * 32 + lane];
        acc[0] = fma2(sdup[nd0 + 0][k], wp, acc[0]);
        acc[1] = fma2(sdup[nd0 + 1][k], wp, acc[1]);
        acc[2] = fma2(sdup[nd0 + 2][k], wp, acc[2]);
        acc[3] = fma2(sdup[nd0 + 3][k], wp, acc[3]);
    }

#pragma unroll
    for (int nd = 0; nd < 4; nd++) {
        int node = base + nd0 + nd;
        if (node < n) {
            float a0, a1;
            unpack2(a0, a1, acc[nd]);
            out[(size_t)node * OD + lane] = a0;
            out[(size_t)node * OD + lane + 32] = a1;
        }
    }
}

extern "C" void kernel_launch(void* const* d_in, const int* in_sizes, int n_in,
                              void* d_out, int out_size) {
    const float* x       = (const float*)d_in[0];
    const float* scalars = (const float*)d_in[1];
    const float* W1      = (const float*)d_in[2];
    const float* b1      = (const float*)d_in[3];
    const float* W2      = (const float*)d_in[4];
    const float* b2      = (const float*)d_in[5];
    const void*  ei      = d_in[6];
    float* out = (float*)d_out;

    int n = in_sizes[0] / XD;   // 50000
    int e = in_sizes[6] / 2;    // 800000

    mega_kernel<<<TOTBLK, 128>>>(x, scalars, W1, b1, ei, n, e);
    gather_kernel<<<(n + 7) / 8, 256>>>(n);
    gemm_kernel<<<(n + 31) / 32, 256>>>(W2, b2, out, n);
}